// round 15
// baseline (speedup 1.0000x reference)
#include <cuda_runtime.h>
#include <cuda_bf16.h>
#include <math.h>

// Fixed shapes: cls_conv_out (4, 1029, 100, 100) fp32; rois (2000,4) int32.
// Only batch 3 used. Output (2000, 21, 1, 1) fp32.
#define KK       7
#define C1       21
#define NJL      49
#define H        100
#define W        100
#define HP       101
#define ROW_S    2124                 // HP*C1=2121 padded to mult of 4 (16B rows)
#define PLANE_S  (HP * ROW_S)
#define IN_BASE  (3 * 1029 * 10000)   // batch 3 offset
#define RPB      4                    // y-rows per block in kernel A

// Integral image, transposed c-innermost: I[jl][y][x][c]; ~42 MB scratch.
__device__ float g_integral[(size_t)NJL * PLANE_S];

// ---------------------------------------------------------------------------
// Kernel A: block = (jl, 4 y-rows), 21 warps = one channel each.
// Scatter STS uses octet-rotated store order: lane group g=lane>>3 writes its
// 4 values in order i=(g+k)&3, making bank = (20*lo + 21*(g+k)) mod 32
// distinct across all 25 lanes at every step (20*lo: 8 multiples of 4;
// 21*(g+k): distinct residues mod 4) -> fully conflict-free (the naive order
// was 4-way conflicted: gcd(84/4*4=20,32)=4).
// All 4 finished rows are stored with ONE 33,984 B cp.async.bulk.
// ---------------------------------------------------------------------------
__global__ void __launch_bounds__(672) build_xsum(const float* __restrict__ in) {
    const int ybase = RPB * blockIdx.x + 1;  // 1, 5, ..., 97
    const int jl    = blockIdx.y;            // 0..48
    const int t     = threadIdx.x;
    const int c     = t >> 5;                // warp id == channel 0..20
    const int lane  = t & 31;
    const int g     = lane >> 3;             // octet 0..3

    __shared__ __align__(16) float smt[RPB][ROW_S];  // final rows: smt[r][x*21+c]

    // zero x=0 column (21 floats) and tail padding (3 floats) of each row buf
    if (t < 24) {
        const int idx = (t < C1) ? t : (2121 + t - C1);
        #pragma unroll
        for (int r = 0; r < RPB; r++) smt[r][idx] = 0.0f;
    }

    // --- loads: lane l holds float4 covering x = 4l..4l+3 of each row
    const float4* src4 = (const float4*)(in + IN_BASE
                        + (size_t)jl * (C1 * H * W) + (size_t)c * (H * W));
    float4 v[RPB];
    if (lane < 25) {
        #pragma unroll
        for (int r = 0; r < RPB; r++)
            v[r] = __ldcs(&src4[(ybase - 1 + r) * (W / 4) + lane]);
    }

    // --- per-row: in-thread scan of 4 + one shfl_up scan over lanes,
    // octet-rotated conflict-free scatter into transposed layout (pos x+1).
    #pragma unroll
    for (int r = 0; r < RPB; r++) {
        float s0 = v[r].x;
        float s1 = s0 + v[r].y;
        float s2 = s1 + v[r].z;
        float s3 = s2 + v[r].w;
        float run = s3;
        #pragma unroll
        for (int d = 1; d < 32; d <<= 1) {
            float u = __shfl_up_sync(0xffffffffu, run, d);
            if (lane >= d) run += u;
        }
        const float off = run - s3;
        if (lane < 25) {
            const float a0 = off + s0, a1 = off + s1, a2 = off + s2, a3 = off + s3;
            float* sl = smt[r] + 84 * lane + C1 + c;
            #pragma unroll
            for (int k = 0; k < 4; k++) {
                const int i = (g + k) & 3;
                const float val = (i == 0) ? a0 : (i == 1) ? a1
                                 : (i == 2) ? a2 : a3;
                sl[i * C1] = val;
            }
        }
    }
    __syncthreads();

    // --- single bulk async store of all 4 contiguous rows (33,984 B)
    if (t == 0) {
        asm volatile("fence.proxy.async.shared::cta;" ::: "memory");
        unsigned sa;
        asm("{ .reg .u64 a; cvta.to.shared.u64 a, %1; cvt.u32.u64 %0, a; }"
            : "=r"(sa) : "l"(&smt[0][0]));
        float* gd = g_integral + ((size_t)jl * HP + ybase) * ROW_S;
        asm volatile(
            "cp.async.bulk.global.shared::cta.bulk_group [%0], [%1], %2;"
            :: "l"(gd), "r"(sa), "r"(RPB * ROW_S * 4) : "memory");
        asm volatile("cp.async.bulk.commit_group;" ::: "memory");
        asm volatile("cp.async.bulk.wait_group 0;" ::: "memory");
    }
}

// ---------------------------------------------------------------------------
// Kernel B: y-cumsum over float2 slots (1062/row); writes y=0 zero row then
// 100 dependent FADD2 steps, unroll 10 for load MLP.
// ---------------------------------------------------------------------------
__global__ void build_ysum() {
    const int jl    = blockIdx.y;
    const int slot2 = blockIdx.x * blockDim.x + threadIdx.x;
    if (slot2 >= ROW_S / 2) return;

    float2* p = (float2*)(g_integral + (size_t)jl * PLANE_S) + slot2;
    const int stride2 = ROW_S / 2;      // 1062

    float2 acc = make_float2(0.f, 0.f);
    p[0] = acc;                         // y = 0 row is zero
    #pragma unroll 10
    for (int y = 1; y <= H; y++) {
        float2 v = p[(size_t)y * stride2];
        acc.x += v.x; acc.y += v.y;
        p[(size_t)y * stride2] = acc;
    }
}

// ---------------------------------------------------------------------------
// Kernel C: one block per ROI. 196 threads precompute the 49x4 corner base
// offsets into smem; main loop is LDS + LDG[base + c]. Register pre-reduction
// (16 jl-groups x 21 c), 21-thread final sum, warp softmax.
// ---------------------------------------------------------------------------
__global__ void __launch_bounds__(352) pool_softmax(const int* __restrict__ rois,
                                                    float* __restrict__ out) {
    const int roi = blockIdx.x;
    const int t   = threadIdx.x;
    __shared__ int   s_base[NJL * 4];  // [jl][corner]: a=y1x1, b=y0x1, d=y1x0, e=y0x0
    __shared__ float s_part[336];
    __shared__ float s_avg[C1];

    const int4 r = ((const int4*)rois)[roi];   // ymin, xmin, ymax, xmax
    const int ys = (r.z - r.x) / KK;
    const int xs = (r.w - r.y) / KK;

    if (t < NJL * 4) {
        const int jl = t >> 2, corner = t & 3;
        const int j = jl / KK, l = jl - j * KK;
        const int y = ((corner & 1) ? (r.x + j * ys) : (r.x + j * ys + ys));
        const int x = ((corner & 2) ? (r.y + l * xs) : (r.y + l * xs + xs));
        s_base[t] = jl * PLANE_S + y * ROW_S + x * C1;
    }
    __syncthreads();

    if (t < 336) {
        const int c   = t % C1;
        const int jl0 = t / C1;   // 0..15
        const float* P = g_integral + c;
        float part = 0.0f;
        #pragma unroll
        for (int jl = jl0; jl < NJL; jl += 16) {
            const int* bp = s_base + 4 * jl;
            const float a = P[bp[0]];
            const float b = P[bp[1]];
            const float d = P[bp[2]];
            const float e = P[bp[3]];
            part += (a - b) - (d - e);
        }
        s_part[t] = part;
    }
    __syncthreads();

    if (t < C1) {
        float acc = 0.0f;
        #pragma unroll
        for (int g = 0; g < 16; g++) acc += s_part[g * C1 + t];
        s_avg[t] = acc / (49.0f * (float)(ys * xs));
    }
    __syncthreads();

    if (t < 32) {
        const bool act = t < C1;
        float v = act ? s_avg[t] : -INFINITY;
        float m = v;
        #pragma unroll
        for (int o = 16; o; o >>= 1) m = fmaxf(m, __shfl_xor_sync(0xffffffffu, m, o));
        float e = act ? expf(v - m) : 0.0f;
        float sum = e;
        #pragma unroll
        for (int o = 16; o; o >>= 1) sum += __shfl_xor_sync(0xffffffffu, sum, o);
        if (act) out[(size_t)roi * C1 + t] = e / sum;
    }
}

// ---------------------------------------------------------------------------
extern "C" void kernel_launch(void* const* d_in, const int* in_sizes, int n_in,
                              void* d_out, int out_size) {
    const float* x    = (const float*)d_in[0];
    const int*   rois = (const int*)d_in[1];
    float*       out  = (float*)d_out;
    const int n_rois  = in_sizes[1] / 4;   // 2000

    dim3 gA(H / RPB, NJL);                  // 25 x 49
    build_xsum<<<gA, 672>>>(x);

    dim3 gB((ROW_S / 2 + 127) / 128, NJL);  // 9 x 49
    build_ysum<<<gB, 128>>>();

    pool_softmax<<<n_rois, 352>>>(rois, out);
}